// round 1
// baseline (speedup 1.0000x reference)
#include <cuda_runtime.h>

#define BB 8192
#define HH 1024
#define KK 1024

// ---------------- scratch (allocation-free: __device__ globals) ----------------
static __device__ float g_Sr[BB * HH];
static __device__ float g_Tr[BB * HH];
static __device__ float g_Su[BB * HH];
static __device__ float g_Tu[BB * HH];
static __device__ float g_Tc[BB * HH];
static __device__ float g_Sc[BB * HH];
static __device__ float g_HR[BB * HH];
static __device__ float g_Ug[BB * HH];

// ---------------- packed f32x2 helpers (Blackwell sm_103a) ----------------
__device__ __forceinline__ unsigned long long ffma2(unsigned long long a,
                                                    unsigned long long b,
                                                    unsigned long long c) {
    unsigned long long d;
    asm("fma.rn.f32x2 %0, %1, %2, %3;" : "=l"(d) : "l"(a), "l"(b), "l"(c));
    return d;
}

__device__ __forceinline__ unsigned long long pack2(float lo, float hi) {
    unsigned long long r;
    asm("mov.b64 %0, {%1, %2};" : "=l"(r) : "f"(lo), "f"(hi));
    return r;
}

// ---------------- SGEMM: C[M,N] = A[M,K] * W[N,K]^T ----------------
// 128x128 tile, BK=16, 256 threads, 8x8 per thread, f32x2 packed FMA.
__global__ __launch_bounds__(256) void sgemm_nt(const float* __restrict__ A,
                                                const float* __restrict__ W,
                                                float* __restrict__ C,
                                                int M, int N, int K) {
    __shared__ float As[16][132];
    __shared__ float Bs[16][132];

    const int tid = threadIdx.x;
    const int bm = blockIdx.y * 128;
    const int bn = blockIdx.x * 128;
    const int tr = tid >> 4;   // 0..15
    const int tc = tid & 15;   // 0..15

    unsigned long long acc[8][4];
#pragma unroll
    for (int i = 0; i < 8; i++)
#pragma unroll
        for (int j = 0; j < 4; j++) acc[i][j] = 0ull;

    const int lr0 = tid >> 2;        // 0..63
    const int lk = (tid & 3) * 4;    // 0,4,8,12

    const float* Aptr = A + (long)(bm + lr0) * K + lk;
    const float* Wptr = W + (long)(bn + lr0) * K + lk;

    for (int k0 = 0; k0 < K; k0 += 16) {
        float4 va0 = *(const float4*)(Aptr + k0);
        float4 va1 = *(const float4*)(Aptr + (long)64 * K + k0);
        float4 vb0 = *(const float4*)(Wptr + k0);
        float4 vb1 = *(const float4*)(Wptr + (long)64 * K + k0);

        As[lk + 0][lr0] = va0.x; As[lk + 1][lr0] = va0.y;
        As[lk + 2][lr0] = va0.z; As[lk + 3][lr0] = va0.w;
        As[lk + 0][lr0 + 64] = va1.x; As[lk + 1][lr0 + 64] = va1.y;
        As[lk + 2][lr0 + 64] = va1.z; As[lk + 3][lr0 + 64] = va1.w;

        Bs[lk + 0][lr0] = vb0.x; Bs[lk + 1][lr0] = vb0.y;
        Bs[lk + 2][lr0] = vb0.z; Bs[lk + 3][lr0] = vb0.w;
        Bs[lk + 0][lr0 + 64] = vb1.x; Bs[lk + 1][lr0 + 64] = vb1.y;
        Bs[lk + 2][lr0 + 64] = vb1.z; Bs[lk + 3][lr0 + 64] = vb1.w;

        __syncthreads();

#pragma unroll
        for (int k = 0; k < 16; k++) {
            float a[8];
            *(float4*)&a[0] = *(const float4*)&As[k][tr * 8];
            *(float4*)&a[4] = *(const float4*)&As[k][tr * 8 + 4];
            unsigned long long b2[4];
#pragma unroll
            for (int j = 0; j < 4; j++)
                b2[j] = *(const unsigned long long*)&Bs[k][tc * 8 + 2 * j];
#pragma unroll
            for (int i = 0; i < 8; i++) {
                unsigned long long aa = pack2(a[i], a[i]);
#pragma unroll
                for (int j = 0; j < 4; j++)
                    acc[i][j] = ffma2(aa, b2[j], acc[i][j]);
            }
        }
        __syncthreads();
    }

#pragma unroll
    for (int i = 0; i < 8; i++) {
        float* crow = C + (long)(bm + tr * 8 + i) * N + bn + tc * 8;
#pragma unroll
        for (int j = 0; j < 4; j++) {
            union { unsigned long long u; float2 f; } cv;
            cv.u = acc[i][j];
            *(float2*)(crow + 2 * j) = cv.f;
        }
    }
}

// ---------------- reductions ----------------
__device__ __forceinline__ float warp_sum(float v) {
#pragma unroll
    for (int o = 16; o > 0; o >>= 1) v += __shfl_xor_sync(0xffffffffu, v, o);
    return v;
}

// Block-reduce 8 partial sums (256 threads). Results broadcast in s[8].
__device__ __forceinline__ void block_reduce8(float* p, float* s, int tid) {
    __shared__ float red[8][8];
    const int lane = tid & 31, w = tid >> 5;
#pragma unroll
    for (int q = 0; q < 8; q++) p[q] = warp_sum(p[q]);
    if (lane == 0) {
#pragma unroll
        for (int q = 0; q < 8; q++) red[q][w] = p[q];
    }
    __syncthreads();
    if (tid < 8) {
        float acc = 0.f;
#pragma unroll
        for (int w2 = 0; w2 < 8; w2++) acc += red[tid][w2];
        red[tid][0] = acc;
    }
    __syncthreads();
#pragma unroll
    for (int q = 0; q < 8; q++) s[q] = red[q][0];
}

__device__ __forceinline__ float sigmoidf_(float z) {
    return 1.0f / (1.0f + expf(-z));
}

// ---------------- gates: r,u from 4 LNs; writes HR = h*r and Ug = u ----------------
__global__ __launch_bounds__(256) void gates_kernel(
    const float* __restrict__ Sr, const float* __restrict__ Tr,
    const float* __restrict__ Su, const float* __restrict__ Tu,
    const float* __restrict__ h,
    const float* __restrict__ gamma, const float* __restrict__ beta,
    float* __restrict__ HR, float* __restrict__ Ug) {
    const int row = blockIdx.x;
    const int tid = threadIdx.x;
    const long base = (long)row * HH;

    float vsr[4], vtr[4], vsu[4], vtu[4];
    float p[8];
#pragma unroll
    for (int q = 0; q < 8; q++) p[q] = 0.f;

#pragma unroll
    for (int j = 0; j < 4; j++) {
        const int c = tid + j * 256;
        float a = Sr[base + c]; vsr[j] = a; p[0] += a; p[1] += a * a;
        float b = Tr[base + c]; vtr[j] = b; p[2] += b; p[3] += b * b;
        float d = Su[base + c]; vsu[j] = d; p[4] += d; p[5] += d * d;
        float e = Tu[base + c]; vtu[j] = e; p[6] += e; p[7] += e * e;
    }

    float s[8];
    block_reduce8(p, s, tid);

    const float inv = 1.0f / (float)HH;
    const float mu0 = s[0] * inv, rs0 = rsqrtf(fmaxf(s[1] * inv - mu0 * mu0, 0.f) + 1e-5f);
    const float mu1 = s[2] * inv, rs1 = rsqrtf(fmaxf(s[3] * inv - mu1 * mu1, 0.f) + 1e-5f);
    const float mu2 = s[4] * inv, rs2 = rsqrtf(fmaxf(s[5] * inv - mu2 * mu2, 0.f) + 1e-5f);
    const float mu3 = s[6] * inv, rs3 = rsqrtf(fmaxf(s[7] * inv - mu3 * mu3, 0.f) + 1e-5f);

#pragma unroll
    for (int j = 0; j < 4; j++) {
        const int c = tid + j * 256;
        const float lnr = (vsr[j] - mu0) * rs0 * gamma[0 * HH + c] + beta[0 * HH + c]
                        + (vtr[j] - mu1) * rs1 * gamma[1 * HH + c] + beta[1 * HH + c];
        const float r = sigmoidf_(lnr);
        const float lnu = (vsu[j] - mu2) * rs2 * gamma[2 * HH + c] + beta[2 * HH + c]
                        + (vtu[j] - mu3) * rs3 * gamma[3 * HH + c] + beta[3 * HH + c];
        const float u = sigmoidf_(lnu);
        HR[base + c] = h[base + c] * r;
        Ug[base + c] = u;
    }
}

// ---------------- final: c = tanh(ln(Sc)+ln(Tc)); out = (1-u)h + u*c ----------------
__global__ __launch_bounds__(256) void final_kernel(
    const float* __restrict__ Sc, const float* __restrict__ Tc,
    const float* __restrict__ h, const float* __restrict__ Ug,
    const float* __restrict__ gamma, const float* __restrict__ beta,
    float* __restrict__ out) {
    const int row = blockIdx.x;
    const int tid = threadIdx.x;
    const long base = (long)row * HH;

    float vsc[4], vtc[4];
    float p[8];
#pragma unroll
    for (int q = 0; q < 8; q++) p[q] = 0.f;

#pragma unroll
    for (int j = 0; j < 4; j++) {
        const int c = tid + j * 256;
        float a = Sc[base + c]; vsc[j] = a; p[0] += a; p[1] += a * a;
        float b = Tc[base + c]; vtc[j] = b; p[2] += b; p[3] += b * b;
    }

    float s[8];
    block_reduce8(p, s, tid);

    const float inv = 1.0f / (float)HH;
    const float mu0 = s[0] * inv, rs0 = rsqrtf(fmaxf(s[1] * inv - mu0 * mu0, 0.f) + 1e-5f);
    const float mu1 = s[2] * inv, rs1 = rsqrtf(fmaxf(s[3] * inv - mu1 * mu1, 0.f) + 1e-5f);

#pragma unroll
    for (int j = 0; j < 4; j++) {
        const int c = tid + j * 256;
        const float lnc = (vsc[j] - mu0) * rs0 * gamma[4 * HH + c] + beta[4 * HH + c]
                        + (vtc[j] - mu1) * rs1 * gamma[5 * HH + c] + beta[5 * HH + c];
        const float cg = tanhf(lnc);
        const float u = Ug[base + c];
        const float hv = h[base + c];
        out[base + c] = (1.0f - u) * hv + u * cg;
    }
}

// ---------------- launch ----------------
extern "C" void kernel_launch(void* const* d_in, const int* in_sizes, int n_in,
                              void* d_out, int out_size) {
    const float* x     = (const float*)d_in[0];
    const float* h     = (const float*)d_in[1];
    const float* W_r   = (const float*)d_in[2];
    const float* U_r   = (const float*)d_in[3];
    const float* W_u   = (const float*)d_in[4];
    const float* U_u   = (const float*)d_in[5];
    const float* W_c   = (const float*)d_in[6];
    const float* U_c   = (const float*)d_in[7];
    const float* gamma = (const float*)d_in[8];
    const float* beta  = (const float*)d_in[9];
    float* out = (float*)d_out;

    float *Sr, *Tr, *Su, *Tu, *Tc, *Sc, *HR, *Ug;
    cudaGetSymbolAddress((void**)&Sr, g_Sr);
    cudaGetSymbolAddress((void**)&Tr, g_Tr);
    cudaGetSymbolAddress((void**)&Su, g_Su);
    cudaGetSymbolAddress((void**)&Tu, g_Tu);
    cudaGetSymbolAddress((void**)&Tc, g_Tc);
    cudaGetSymbolAddress((void**)&Sc, g_Sc);
    cudaGetSymbolAddress((void**)&HR, g_HR);
    cudaGetSymbolAddress((void**)&Ug, g_Ug);

    dim3 grid(HH / 128, BB / 128);
    dim3 blk(256);

    // 5 independent GEMMs
    sgemm_nt<<<grid, blk>>>(h, W_r, Sr, BB, HH, KK);
    sgemm_nt<<<grid, blk>>>(x, U_r, Tr, BB, HH, KK);
    sgemm_nt<<<grid, blk>>>(h, W_u, Su, BB, HH, KK);
    sgemm_nt<<<grid, blk>>>(x, U_u, Tu, BB, HH, KK);
    sgemm_nt<<<grid, blk>>>(x, U_c, Tc, BB, HH, KK);

    // gates: r,u ; HR = h*r
    gates_kernel<<<BB, blk>>>(Sr, Tr, Su, Tu, h, gamma, beta, HR, Ug);

    // dependent GEMM
    sgemm_nt<<<grid, blk>>>(HR, W_c, Sc, BB, HH, KK);

    // final blend
    final_kernel<<<BB, blk>>>(Sc, Tc, h, Ug, gamma, beta, out);
}

// round 3
// speedup vs baseline: 2.1587x; 2.1587x over previous
#include <cuda_runtime.h>
#include <cuda_bf16.h>
#include <cstdint>

#define BB 8192
#define HH 1024
#define KK 1024

// ---------------- scratch (__device__ globals; allocation-free) ----------------
static __device__ float g_Sr[BB * HH];
static __device__ float g_Tr[BB * HH];
static __device__ float g_Su[BB * HH];
static __device__ float g_Tu[BB * HH];
static __device__ float g_Tc[BB * HH];
static __device__ float g_Sc[BB * HH];
static __device__ float g_Ug[BB * HH];

static __device__ __nv_bfloat16 g_xhi[BB * KK], g_xlo[BB * KK];
static __device__ __nv_bfloat16 g_hhi[BB * HH], g_hlo[BB * HH];
static __device__ __nv_bfloat16 g_hrhi[BB * HH], g_hrlo[BB * HH];
static __device__ __nv_bfloat16 g_Whi[6][HH * KK], g_Wlo[6][HH * KK];

// ---------------- PTX helpers (base ISA only: compute_103-safe) ----------------
__device__ __forceinline__ uint32_t smem_u32(const void* p) {
    uint32_t a;
    asm("{ .reg .u64 t; cvta.to.shared.u64 t, %1; cvt.u32.u64 %0, t; }" : "=r"(a) : "l"(p));
    return a;
}

#define CP_ASYNC16(dst, src) \
    asm volatile("cp.async.cg.shared.global [%0], [%1], 16;" :: "r"(dst), "l"(src))
#define CP_COMMIT() asm volatile("cp.async.commit_group;" ::: "memory")
#define CP_WAIT(n) asm volatile("cp.async.wait_group %0;" :: "n"(n) : "memory")

__device__ __forceinline__ void ldsm_x4(uint32_t* r, uint32_t a) {
    asm volatile("ldmatrix.sync.aligned.m8n8.x4.shared.b16 {%0,%1,%2,%3}, [%4];"
                 : "=r"(r[0]), "=r"(r[1]), "=r"(r[2]), "=r"(r[3]) : "r"(a));
}
__device__ __forceinline__ void ldsm_x2(uint32_t* r, uint32_t a) {
    asm volatile("ldmatrix.sync.aligned.m8n8.x2.shared.b16 {%0,%1}, [%2];"
                 : "=r"(r[0]), "=r"(r[1]) : "r"(a));
}

__device__ __forceinline__ void mma16816(float* d, const uint32_t* a, const uint32_t* b) {
    asm volatile(
        "mma.sync.aligned.m16n8k16.row.col.f32.bf16.bf16.f32 "
        "{%0,%1,%2,%3}, {%4,%5,%6,%7}, {%8,%9}, {%0,%1,%2,%3};"
        : "+f"(d[0]), "+f"(d[1]), "+f"(d[2]), "+f"(d[3])
        : "r"(a[0]), "r"(a[1]), "r"(a[2]), "r"(a[3]), "r"(b[0]), "r"(b[1]));
}

// ---------------- split-bf16 mma.sync GEMM ----------------
// C[M,N] = A[M,K] * W[N,K]^T in fp32 via bf16 hi/lo 3-pass split.
// Tile 128x128x32, 256 threads (warps 2Mx4N, warp tile 64x32), cp.async x2 stages.
#define BM 128
#define BN 128
#define BK 32
#define NCHUNK (KK / BK)          // 32
#define RSTRIDE 80                // bytes per SMEM row: 64B data + 16B pad (conflict-free ldmatrix)
#define T_BYTES (128 * RSTRIDE)   // 10240 per tensor tile
#define OFF_AHI 0
#define OFF_ALO (1 * T_BYTES)
#define OFF_BHI (2 * T_BYTES)
#define OFF_BLO (3 * T_BYTES)
#define STAGE_BYTES (4 * T_BYTES) // 40960
#define GEMM_SMEM (2 * STAGE_BYTES)

__device__ __forceinline__ void load_stage(
    uint32_t sb, int stage, int kc, int tid, int bm, int bn,
    const __nv_bfloat16* __restrict__ Ahi, const __nv_bfloat16* __restrict__ Alo,
    const __nv_bfloat16* __restrict__ Bhi, const __nv_bfloat16* __restrict__ Blo) {
    const uint32_t su = sb + stage * STAGE_BYTES;
    const int row = tid >> 1;
    const int ch = (tid & 1) * 2;                 // 16B chunk 0 or 2
    const long koff = (long)kc * BK + ch * 8;     // element offset in K
    const uint32_t doff = row * RSTRIDE + ch * 16;

    const char* ga = (const char*)(Ahi + (long)(bm + row) * KK + koff);
    const char* gal = (const char*)(Alo + (long)(bm + row) * KK + koff);
    const char* gb = (const char*)(Bhi + (long)(bn + row) * KK + koff);
    const char* gbl = (const char*)(Blo + (long)(bn + row) * KK + koff);

    CP_ASYNC16(su + OFF_AHI + doff, ga);       CP_ASYNC16(su + OFF_AHI + doff + 16, ga + 16);
    CP_ASYNC16(su + OFF_ALO + doff, gal);      CP_ASYNC16(su + OFF_ALO + doff + 16, gal + 16);
    CP_ASYNC16(su + OFF_BHI + doff, gb);       CP_ASYNC16(su + OFF_BHI + doff + 16, gb + 16);
    CP_ASYNC16(su + OFF_BLO + doff, gbl);      CP_ASYNC16(su + OFF_BLO + doff + 16, gbl + 16);
}

__global__ __launch_bounds__(256, 2) void gemm_split(
    const __nv_bfloat16* __restrict__ Ahi, const __nv_bfloat16* __restrict__ Alo,
    const __nv_bfloat16* __restrict__ Bhi, const __nv_bfloat16* __restrict__ Blo,
    float* __restrict__ C) {
    extern __shared__ char smem[];
    const uint32_t sb = smem_u32(smem);
    const int tid = threadIdx.x;
    const int wid = tid >> 5, lane = tid & 31;
    const int warp_m = wid >> 2;   // 0..1
    const int warp_n = wid & 3;    // 0..3
    const int bm = blockIdx.y * BM;
    const int bn = blockIdx.x * BN;

    float acc[4][4][4];
#pragma unroll
    for (int i = 0; i < 4; i++)
#pragma unroll
        for (int j = 0; j < 4; j++)
#pragma unroll
            for (int q = 0; q < 4; q++) acc[i][j][q] = 0.f;

    // per-lane ldmatrix row offsets (constant across chunks)
    const uint32_t a_row = (warp_m * 64 + (lane & 15)) * RSTRIDE;
    const uint32_t a_ch16 = (lane >> 4) * 16;          // k-half within kstep
    const uint32_t b_row = (warp_n * 32 + (lane & 7)) * RSTRIDE;
    const uint32_t b_ch16 = ((lane >> 3) & 1) * 16;

    load_stage(sb, 0, 0, tid, bm, bn, Ahi, Alo, Bhi, Blo);
    CP_COMMIT();
    load_stage(sb, 1, 1, tid, bm, bn, Ahi, Alo, Bhi, Blo);
    CP_COMMIT();

    for (int c = 0; c < NCHUNK; c++) {
        if (c + 2 < NCHUNK) { CP_WAIT(1); } else { CP_WAIT(0); }
        __syncthreads();

        const uint32_t su = sb + (c & 1) * STAGE_BYTES;
#pragma unroll
        for (int ks = 0; ks < 2; ks++) {
            const uint32_t kbase = ks * 32;  // 2 chunks of 16B per kstep

            uint32_t ah[4][4];
#pragma unroll
            for (int mt = 0; mt < 4; mt++)
                ldsm_x4(ah[mt], su + OFF_AHI + a_row + mt * 16 * RSTRIDE + kbase + a_ch16);
            uint32_t bh[4][2];
#pragma unroll
            for (int nt = 0; nt < 4; nt++)
                ldsm_x2(bh[nt], su + OFF_BHI + b_row + nt * 8 * RSTRIDE + kbase + b_ch16);
#pragma unroll
            for (int mt = 0; mt < 4; mt++)
#pragma unroll
                for (int nt = 0; nt < 4; nt++) mma16816(acc[mt][nt], ah[mt], bh[nt]);

            uint32_t bl[4][2];
#pragma unroll
            for (int nt = 0; nt < 4; nt++)
                ldsm_x2(bl[nt], su + OFF_BLO + b_row + nt * 8 * RSTRIDE + kbase + b_ch16);
#pragma unroll
            for (int mt = 0; mt < 4; mt++)
#pragma unroll
                for (int nt = 0; nt < 4; nt++) mma16816(acc[mt][nt], ah[mt], bl[nt]);

            uint32_t al[4][4];
#pragma unroll
            for (int mt = 0; mt < 4; mt++)
                ldsm_x4(al[mt], su + OFF_ALO + a_row + mt * 16 * RSTRIDE + kbase + a_ch16);
#pragma unroll
            for (int mt = 0; mt < 4; mt++)
#pragma unroll
                for (int nt = 0; nt < 4; nt++) mma16816(acc[mt][nt], al[mt], bh[nt]);
        }

        __syncthreads();
        if (c + 2 < NCHUNK) {
            load_stage(sb, c & 1, c + 2, tid, bm, bn, Ahi, Alo, Bhi, Blo);
            CP_COMMIT();
        }
    }

    // epilogue
    const int gid = lane >> 2, tig = lane & 3;
#pragma unroll
    for (int mt = 0; mt < 4; mt++) {
        const int row0 = bm + warp_m * 64 + mt * 16 + gid;
#pragma unroll
        for (int nt = 0; nt < 4; nt++) {
            const int col = bn + warp_n * 32 + nt * 8 + tig * 2;
            float2 v0 = make_float2(acc[mt][nt][0], acc[mt][nt][1]);
            float2 v1 = make_float2(acc[mt][nt][2], acc[mt][nt][3]);
            *(float2*)(C + (long)row0 * HH + col) = v0;
            *(float2*)(C + (long)(row0 + 8) * HH + col) = v1;
        }
    }
}

// ---------------- fp32 -> bf16 hi/lo split ----------------
__global__ __launch_bounds__(256) void split_kernel(const float4* __restrict__ src,
                                                    uint2* __restrict__ hi,
                                                    uint2* __restrict__ lo, int n4) {
    int i = blockIdx.x * blockDim.x + threadIdx.x;
    if (i >= n4) return;
    float4 v = src[i];
    __nv_bfloat16 h0 = __float2bfloat16(v.x), h1 = __float2bfloat16(v.y);
    __nv_bfloat16 h2 = __float2bfloat16(v.z), h3 = __float2bfloat16(v.w);
    __nv_bfloat16 l0 = __float2bfloat16(v.x - __bfloat162float(h0));
    __nv_bfloat16 l1 = __float2bfloat16(v.y - __bfloat162float(h1));
    __nv_bfloat16 l2 = __float2bfloat16(v.z - __bfloat162float(h2));
    __nv_bfloat16 l3 = __float2bfloat16(v.w - __bfloat162float(h3));
    __nv_bfloat162 ha(h0, h1), hb(h2, h3), la(l0, l1), lb(l2, l3);
    uint2 ho, loo;
    ho.x = *(uint32_t*)&ha; ho.y = *(uint32_t*)&hb;
    loo.x = *(uint32_t*)&la; loo.y = *(uint32_t*)&lb;
    hi[i] = ho;
    lo[i] = loo;
}

// ---------------- reductions ----------------
__device__ __forceinline__ float warp_sum(float v) {
#pragma unroll
    for (int o = 16; o > 0; o >>= 1) v += __shfl_xor_sync(0xffffffffu, v, o);
    return v;
}

__device__ __forceinline__ void block_reduce8(float* p, float* s, int tid) {
    __shared__ float red[8][8];
    const int lane = tid & 31, w = tid >> 5;
#pragma unroll
    for (int q = 0; q < 8; q++) p[q] = warp_sum(p[q]);
    if (lane == 0) {
#pragma unroll
        for (int q = 0; q < 8; q++) red[q][w] = p[q];
    }
    __syncthreads();
    if (tid < 8) {
        float acc = 0.f;
#pragma unroll
        for (int w2 = 0; w2 < 8; w2++) acc += red[tid][w2];
        red[tid][0] = acc;
    }
    __syncthreads();
#pragma unroll
    for (int q = 0; q < 8; q++) s[q] = red[q][0];
}

__device__ __forceinline__ float sigmoidf_(float z) { return 1.0f / (1.0f + expf(-z)); }

// ---------------- gates: r,u; HR = h*r emitted as bf16 hi/lo ----------------
__global__ __launch_bounds__(256) void gates_kernel(
    const float* __restrict__ Sr, const float* __restrict__ Tr,
    const float* __restrict__ Su, const float* __restrict__ Tu,
    const float* __restrict__ h,
    const float* __restrict__ gamma, const float* __restrict__ beta,
    __nv_bfloat16* __restrict__ HRhi, __nv_bfloat16* __restrict__ HRlo,
    float* __restrict__ Ug) {
    const int row = blockIdx.x;
    const int tid = threadIdx.x;
    const long base = (long)row * HH;

    float vsr[4], vtr[4], vsu[4], vtu[4];
    float p[8];
#pragma unroll
    for (int q = 0; q < 8; q++) p[q] = 0.f;

#pragma unroll
    for (int j = 0; j < 4; j++) {
        const int c = tid + j * 256;
        float a = Sr[base + c]; vsr[j] = a; p[0] += a; p[1] += a * a;
        float b = Tr[base + c]; vtr[j] = b; p[2] += b; p[3] += b * b;
        float d = Su[base + c]; vsu[j] = d; p[4] += d; p[5] += d * d;
        float e = Tu[base + c]; vtu[j] = e; p[6] += e; p[7] += e * e;
    }

    float s[8];
    block_reduce8(p, s, tid);

    const float inv = 1.0f / (float)HH;
    const float mu0 = s[0] * inv, rs0 = rsqrtf(fmaxf(s[1] * inv - mu0 * mu0, 0.f) + 1e-5f);
    const float mu1 = s[2] * inv, rs1 = rsqrtf(fmaxf(s[3] * inv - mu1 * mu1, 0.f) + 1e-5f);
    const float mu2 = s[4] * inv, rs2 = rsqrtf(fmaxf(s[5] * inv - mu2 * mu2, 0.f) + 1e-5f);
    const float mu3 = s[6] * inv, rs3 = rsqrtf(fmaxf(s[7] * inv - mu3 * mu3, 0.f) + 1e-5f);

#pragma unroll
    for (int j = 0; j < 4; j++) {
        const int c = tid + j * 256;
        const float lnr = (vsr[j] - mu0) * rs0 * gamma[0 * HH + c] + beta[0 * HH + c]
                        + (vtr[j] - mu1) * rs1 * gamma[1 * HH + c] + beta[1 * HH + c];
        const float r = sigmoidf_(lnr);
        const float lnu = (vsu[j] - mu2) * rs2 * gamma[2 * HH + c] + beta[2 * HH + c]
                        + (vtu[j] - mu3) * rs3 * gamma[3 * HH + c] + beta[3 * HH + c];
        const float u = sigmoidf_(lnu);
        const float hr = h[base + c] * r;
        __nv_bfloat16 hh = __float2bfloat16(hr);
        HRhi[base + c] = hh;
        HRlo[base + c] = __float2bfloat16(hr - __bfloat162float(hh));
        Ug[base + c] = u;
    }
}

// ---------------- final: c = tanh(ln+ln); out = (1-u)h + u*c ----------------
__global__ __launch_bounds__(256) void final_kernel(
    const float* __restrict__ Sc, const float* __restrict__ Tc,
    const float* __restrict__ h, const float* __restrict__ Ug,
    const float* __restrict__ gamma, const float* __restrict__ beta,
    float* __restrict__ out) {
    const int row = blockIdx.x;
    const int tid = threadIdx.x;
    const long base = (long)row * HH;

    float vsc[4], vtc[4];
    float p[8];
#pragma unroll
    for (int q = 0; q < 8; q++) p[q] = 0.f;

#pragma unroll
    for (int j = 0; j < 4; j++) {
        const int c = tid + j * 256;
        float a = Sc[base + c]; vsc[j] = a; p[0] += a; p[1] += a * a;
        float b = Tc[base + c]; vtc[j] = b; p[2] += b; p[3] += b * b;
    }

    float s[8];
    block_reduce8(p, s, tid);

    const float inv = 1.0f / (float)HH;
    const float mu0 = s[0] * inv, rs0 = rsqrtf(fmaxf(s[1] * inv - mu0 * mu0, 0.f) + 1e-5f);
    const float mu1 = s[2] * inv, rs1 = rsqrtf(fmaxf(s[3] * inv - mu1 * mu1, 0.f) + 1e-5f);

#pragma unroll
    for (int j = 0; j < 4; j++) {
        const int c = tid + j * 256;
        const float lnc = (vsc[j] - mu0) * rs0 * gamma[4 * HH + c] + beta[4 * HH + c]
                        + (vtc[j] - mu1) * rs1 * gamma[5 * HH + c] + beta[5 * HH + c];
        const float cg = tanhf(lnc);
        const float u = Ug[base + c];
        const float hv = h[base + c];
        out[base + c] = (1.0f - u) * hv + u * cg;
    }
}

// ---------------- launch ----------------
extern "C" void kernel_launch(void* const* d_in, const int* in_sizes, int n_in,
                              void* d_out, int out_size) {
    const float* x     = (const float*)d_in[0];
    const float* h     = (const float*)d_in[1];
    const float* W[6]  = {(const float*)d_in[2], (const float*)d_in[3],
                          (const float*)d_in[4], (const float*)d_in[5],
                          (const float*)d_in[6], (const float*)d_in[7]};
    const float* gamma = (const float*)d_in[8];
    const float* beta  = (const float*)d_in[9];
    float* out = (float*)d_out;

    float *Sr, *Tr, *Su, *Tu, *Tc, *Sc, *Ug;
    cudaGetSymbolAddress((void**)&Sr, g_Sr);
    cudaGetSymbolAddress((void**)&Tr, g_Tr);
    cudaGetSymbolAddress((void**)&Su, g_Su);
    cudaGetSymbolAddress((void**)&Tu, g_Tu);
    cudaGetSymbolAddress((void**)&Tc, g_Tc);
    cudaGetSymbolAddress((void**)&Sc, g_Sc);
    cudaGetSymbolAddress((void**)&Ug, g_Ug);

    __nv_bfloat16 *xhi, *xlo, *hhi, *hlo, *hrhi, *hrlo, *Whi, *Wlo;
    cudaGetSymbolAddress((void**)&xhi, g_xhi);
    cudaGetSymbolAddress((void**)&xlo, g_xlo);
    cudaGetSymbolAddress((void**)&hhi, g_hhi);
    cudaGetSymbolAddress((void**)&hlo, g_hlo);
    cudaGetSymbolAddress((void**)&hrhi, g_hrhi);
    cudaGetSymbolAddress((void**)&hrlo, g_hrlo);
    cudaGetSymbolAddress((void**)&Whi, g_Whi);
    cudaGetSymbolAddress((void**)&Wlo, g_Wlo);

    cudaFuncSetAttribute(gemm_split, cudaFuncAttributeMaxDynamicSharedMemorySize, GEMM_SMEM);

    // splits
    {
        int n4 = BB * KK / 4;
        split_kernel<<<(n4 + 255) / 256, 256>>>((const float4*)x, (uint2*)xhi, (uint2*)xlo, n4);
        split_kernel<<<(n4 + 255) / 256, 256>>>((const float4*)h, (uint2*)hhi, (uint2*)hlo, n4);
        int w4 = HH * KK / 4;
        for (int i = 0; i < 6; i++)
            split_kernel<<<(w4 + 255) / 256, 256>>>((const float4*)W[i],
                                                    (uint2*)(Whi + (long)i * HH * KK),
                                                    (uint2*)(Wlo + (long)i * HH * KK), w4);
    }

    dim3 gg(HH / BN, BB / BM);  // (8, 64)

    // W order: W_r, U_r, W_u, U_u, W_c, U_c -> indices 0..5
    gemm_split<<<gg, 256, GEMM_SMEM>>>(hhi, hlo, Whi + 0L * HH * KK, Wlo + 0L * HH * KK, Sr);
    gemm_split<<<gg, 256, GEMM_SMEM>>>(xhi, xlo, Whi + 1L * HH * KK, Wlo + 1L * HH * KK, Tr);
    gemm_split<<<gg, 256, GEMM_SMEM>>>(hhi, hlo, Whi + 2L * HH * KK, Wlo + 2L * HH * KK, Su);
    gemm_split<<<gg, 256, GEMM_SMEM>>>(xhi, xlo, Whi + 3L * HH * KK, Wlo + 3L * HH * KK, Tu);
    gemm_split<<<gg, 256, GEMM_SMEM>>>(xhi, xlo, Whi + 5L * HH * KK, Wlo + 5L * HH * KK, Tc);

    gates_kernel<<<BB, 256>>>(Sr, Tr, Su, Tu, h, gamma, beta, hrhi, hrlo, Ug);

    gemm_split<<<gg, 256, GEMM_SMEM>>>(hrhi, hrlo, Whi + 4L * HH * KK, Wlo + 4L * HH * KK, Sc);

    final_kernel<<<BB, 256>>>(Sc, Tc, h, Ug, gamma, beta, out);
}

// round 4
// speedup vs baseline: 4.7187x; 2.1859x over previous
#include <cuda_runtime.h>
#include <cuda_fp16.h>
#include <cstdint>

#define BB 8192
#define HH 1024
#define KK 1024

// ---------------- scratch (__device__ globals; allocation-free) ----------------
static __device__ float g_Sr[BB * HH];
static __device__ float g_Tr[BB * HH];
static __device__ float g_Su[BB * HH];
static __device__ float g_Tu[BB * HH];
static __device__ float g_Tc[BB * HH];
static __device__ float g_Sc[BB * HH];
static __device__ float g_Ug[BB * HH];

static __device__ __half g_xh[BB * KK];
static __device__ __half g_hh[BB * HH];
static __device__ __half g_hrh[BB * HH];
static __device__ __half g_Wh[6][HH * KK];

// ---------------- PTX helpers (base ISA only: compute_103-safe) ----------------
__device__ __forceinline__ uint32_t smem_u32(const void* p) {
    uint32_t a;
    asm("{ .reg .u64 t; cvta.to.shared.u64 t, %1; cvt.u32.u64 %0, t; }" : "=r"(a) : "l"(p));
    return a;
}

#define CP_ASYNC16(dst, src) \
    asm volatile("cp.async.cg.shared.global [%0], [%1], 16;" :: "r"(dst), "l"(src))
#define CP_COMMIT() asm volatile("cp.async.commit_group;" ::: "memory")
#define CP_WAIT(n) asm volatile("cp.async.wait_group %0;" :: "n"(n) : "memory")

__device__ __forceinline__ void ldsm_x4(uint32_t* r, uint32_t a) {
    asm volatile("ldmatrix.sync.aligned.m8n8.x4.shared.b16 {%0,%1,%2,%3}, [%4];"
                 : "=r"(r[0]), "=r"(r[1]), "=r"(r[2]), "=r"(r[3]) : "r"(a));
}
__device__ __forceinline__ void ldsm_x2(uint32_t* r, uint32_t a) {
    asm volatile("ldmatrix.sync.aligned.m8n8.x2.shared.b16 {%0,%1}, [%2];"
                 : "=r"(r[0]), "=r"(r[1]) : "r"(a));
}

__device__ __forceinline__ void mma16816(float* d, const uint32_t* a, const uint32_t* b) {
    asm volatile(
        "mma.sync.aligned.m16n8k16.row.col.f32.f16.f16.f32 "
        "{%0,%1,%2,%3}, {%4,%5,%6,%7}, {%8,%9}, {%0,%1,%2,%3};"
        : "+f"(d[0]), "+f"(d[1]), "+f"(d[2]), "+f"(d[3])
        : "r"(a[0]), "r"(a[1]), "r"(a[2]), "r"(a[3]), "r"(b[0]), "r"(b[1]));
}

// ---------------- single-pass fp16 mma.sync GEMM ----------------
// C[M,N] = A[M,K] * W[N,K]^T, fp16 inputs, fp32 accumulate.
// Tile 128x128x32, 256 threads (warps 2Mx4N, warp tile 64x32), 3-stage cp.async.
#define BM 128
#define BN 128
#define BK 32
#define NCHUNK (KK / BK)          // 32
#define NSTAGE 3
#define RSTRIDE 80                // 64B data + 16B pad -> conflict-free ldmatrix phases
#define T_BYTES (128 * RSTRIDE)   // 10240 per tensor tile
#define OFF_A 0
#define OFF_B T_BYTES
#define STAGE_BYTES (2 * T_BYTES) // 20480
#define GEMM_SMEM (NSTAGE * STAGE_BYTES)  // 61440

__device__ __forceinline__ void load_stage(
    uint32_t sb, int stage, int kc, int tid, int bm, int bn,
    const __half* __restrict__ A, const __half* __restrict__ B) {
    const uint32_t su = sb + stage * STAGE_BYTES;
    const int row = tid >> 1;
    const int ch = (tid & 1) * 2;                 // 16B chunk 0 or 2
    const long koff = (long)kc * BK + ch * 8;     // element offset in K
    const uint32_t doff = row * RSTRIDE + ch * 16;

    const char* ga = (const char*)(A + (long)(bm + row) * KK + koff);
    const char* gb = (const char*)(B + (long)(bn + row) * KK + koff);

    CP_ASYNC16(su + OFF_A + doff, ga);   CP_ASYNC16(su + OFF_A + doff + 16, ga + 16);
    CP_ASYNC16(su + OFF_B + doff, gb);   CP_ASYNC16(su + OFF_B + doff + 16, gb + 16);
}

__global__ __launch_bounds__(256, 2) void gemm_h(
    const __half* __restrict__ A, const __half* __restrict__ B,
    float* __restrict__ C) {
    extern __shared__ char smem[];
    const uint32_t sb = smem_u32(smem);
    const int tid = threadIdx.x;
    const int wid = tid >> 5, lane = tid & 31;
    const int warp_m = wid >> 2;   // 0..1
    const int warp_n = wid & 3;    // 0..3
    const int bm = blockIdx.y * BM;
    const int bn = blockIdx.x * BN;

    float acc[4][4][4];
#pragma unroll
    for (int i = 0; i < 4; i++)
#pragma unroll
        for (int j = 0; j < 4; j++)
#pragma unroll
            for (int q = 0; q < 4; q++) acc[i][j][q] = 0.f;

    const uint32_t a_row = (warp_m * 64 + (lane & 15)) * RSTRIDE;
    const uint32_t a_ch16 = (lane >> 4) * 16;
    const uint32_t b_row = (warp_n * 32 + (lane & 7)) * RSTRIDE;
    const uint32_t b_ch16 = ((lane >> 3) & 1) * 16;

#pragma unroll
    for (int s = 0; s < NSTAGE; s++) {
        load_stage(sb, s, s, tid, bm, bn, A, B);
        CP_COMMIT();
    }

    for (int c = 0; c < NCHUNK; c++) {
        CP_WAIT(NSTAGE - 1);
        __syncthreads();

        const uint32_t su = sb + (c % NSTAGE) * STAGE_BYTES;
#pragma unroll
        for (int ks = 0; ks < 2; ks++) {
            const uint32_t kbase = ks * 32;

            uint32_t ah[4][4];
#pragma unroll
            for (int mt = 0; mt < 4; mt++)
                ldsm_x4(ah[mt], su + OFF_A + a_row + mt * 16 * RSTRIDE + kbase + a_ch16);
            uint32_t bh[4][2];
#pragma unroll
            for (int nt = 0; nt < 4; nt++)
                ldsm_x2(bh[nt], su + OFF_B + b_row + nt * 8 * RSTRIDE + kbase + b_ch16);
#pragma unroll
            for (int mt = 0; mt < 4; mt++)
#pragma unroll
                for (int nt = 0; nt < 4; nt++) mma16816(acc[mt][nt], ah[mt], bh[nt]);
        }

        __syncthreads();
        if (c + NSTAGE < NCHUNK)
            load_stage(sb, (c + NSTAGE) % NSTAGE, c + NSTAGE, tid, bm, bn, A, B);
        CP_COMMIT();  // always commit (possibly empty) to keep group counting exact
    }

    // epilogue
    const int gid = lane >> 2, tig = lane & 3;
#pragma unroll
    for (int mt = 0; mt < 4; mt++) {
        const int row0 = bm + warp_m * 64 + mt * 16 + gid;
#pragma unroll
        for (int nt = 0; nt < 4; nt++) {
            const int col = bn + warp_n * 32 + nt * 8 + tig * 2;
            *(float2*)(C + (long)row0 * HH + col) = make_float2(acc[mt][nt][0], acc[mt][nt][1]);
            *(float2*)(C + (long)(row0 + 8) * HH + col) = make_float2(acc[mt][nt][2], acc[mt][nt][3]);
        }
    }
}

// ---------------- fp32 -> fp16 convert ----------------
__global__ __launch_bounds__(256) void tohalf_kernel(const float4* __restrict__ src,
                                                     uint2* __restrict__ dst, int n4) {
    int i = blockIdx.x * blockDim.x + threadIdx.x;
    if (i >= n4) return;
    float4 v = src[i];
    __half2 a = __floats2half2_rn(v.x, v.y);
    __half2 b = __floats2half2_rn(v.z, v.w);
    uint2 o;
    o.x = *(uint32_t*)&a;
    o.y = *(uint32_t*)&b;
    dst[i] = o;
}

// ---------------- reductions ----------------
__device__ __forceinline__ float warp_sum(float v) {
#pragma unroll
    for (int o = 16; o > 0; o >>= 1) v += __shfl_xor_sync(0xffffffffu, v, o);
    return v;
}

__device__ __forceinline__ void block_reduce8(float* p, float* s, int tid) {
    __shared__ float red[8][8];
    const int lane = tid & 31, w = tid >> 5;
#pragma unroll
    for (int q = 0; q < 8; q++) p[q] = warp_sum(p[q]);
    if (lane == 0) {
#pragma unroll
        for (int q = 0; q < 8; q++) red[q][w] = p[q];
    }
    __syncthreads();
    if (tid < 8) {
        float acc = 0.f;
#pragma unroll
        for (int w2 = 0; w2 < 8; w2++) acc += red[tid][w2];
        red[tid][0] = acc;
    }
    __syncthreads();
#pragma unroll
    for (int q = 0; q < 8; q++) s[q] = red[q][0];
}

__device__ __forceinline__ float sigmoidf_(float z) { return 1.0f / (1.0f + expf(-z)); }

// ---------------- gates: r,u; HR = h*r emitted as fp16 ----------------
__global__ __launch_bounds__(256) void gates_kernel(
    const float* __restrict__ Sr, const float* __restrict__ Tr,
    const float* __restrict__ Su, const float* __restrict__ Tu,
    const float* __restrict__ h,
    const float* __restrict__ gamma, const float* __restrict__ beta,
    __half* __restrict__ HRh, float* __restrict__ Ug) {
    const int row = blockIdx.x;
    const int tid = threadIdx.x;
    const long base = (long)row * HH;

    float vsr[4], vtr[4], vsu[4], vtu[4];
    float p[8];
#pragma unroll
    for (int q = 0; q < 8; q++) p[q] = 0.f;

#pragma unroll
    for (int j = 0; j < 4; j++) {
        const int c = tid + j * 256;
        float a = Sr[base + c]; vsr[j] = a; p[0] += a; p[1] += a * a;
        float b = Tr[base + c]; vtr[j] = b; p[2] += b; p[3] += b * b;
        float d = Su[base + c]; vsu[j] = d; p[4] += d; p[5] += d * d;
        float e = Tu[base + c]; vtu[j] = e; p[6] += e; p[7] += e * e;
    }

    float s[8];
    block_reduce8(p, s, tid);

    const float inv = 1.0f / (float)HH;
    const float mu0 = s[0] * inv, rs0 = rsqrtf(fmaxf(s[1] * inv - mu0 * mu0, 0.f) + 1e-5f);
    const float mu1 = s[2] * inv, rs1 = rsqrtf(fmaxf(s[3] * inv - mu1 * mu1, 0.f) + 1e-5f);
    const float mu2 = s[4] * inv, rs2 = rsqrtf(fmaxf(s[5] * inv - mu2 * mu2, 0.f) + 1e-5f);
    const float mu3 = s[6] * inv, rs3 = rsqrtf(fmaxf(s[7] * inv - mu3 * mu3, 0.f) + 1e-5f);

#pragma unroll
    for (int j = 0; j < 4; j++) {
        const int c = tid + j * 256;
        const float lnr = (vsr[j] - mu0) * rs0 * gamma[0 * HH + c] + beta[0 * HH + c]
                        + (vtr[j] - mu1) * rs1 * gamma[1 * HH + c] + beta[1 * HH + c];
        const float r = sigmoidf_(lnr);
        const float lnu = (vsu[j] - mu2) * rs2 * gamma[2 * HH + c] + beta[2 * HH + c]
                        + (vtu[j] - mu3) * rs3 * gamma[3 * HH + c] + beta[3 * HH + c];
        const float u = sigmoidf_(lnu);
        const float hr = h[base + c] * r;
        HRh[base + c] = __float2half_rn(hr);
        Ug[base + c] = u;
    }
}

// ---------------- final: c = tanh(ln+ln); out = (1-u)h + u*c ----------------
__global__ __launch_bounds__(256) void final_kernel(
    const float* __restrict__ Sc, const float* __restrict__ Tc,
    const float* __restrict__ h, const float* __restrict__ Ug,
    const float* __restrict__ gamma, const float* __restrict__ beta,
    float* __restrict__ out) {
    const int row = blockIdx.x;
    const int tid = threadIdx.x;
    const long base = (long)row * HH;

    float vsc[4], vtc[4];
    float p[8];
#pragma unroll
    for (int q = 0; q < 8; q++) p[q] = 0.f;

#pragma unroll
    for (int j = 0; j < 4; j++) {
        const int c = tid + j * 256;
        float a = Sc[base + c]; vsc[j] = a; p[0] += a; p[1] += a * a;
        float b = Tc[base + c]; vtc[j] = b; p[2] += b; p[3] += b * b;
    }

    float s[8];
    block_reduce8(p, s, tid);

    const float inv = 1.0f / (float)HH;
    const float mu0 = s[0] * inv, rs0 = rsqrtf(fmaxf(s[1] * inv - mu0 * mu0, 0.f) + 1e-5f);
    const float mu1 = s[2] * inv, rs1 = rsqrtf(fmaxf(s[3] * inv - mu1 * mu1, 0.f) + 1e-5f);

#pragma unroll
    for (int j = 0; j < 4; j++) {
        const int c = tid + j * 256;
        const float lnc = (vsc[j] - mu0) * rs0 * gamma[4 * HH + c] + beta[4 * HH + c]
                        + (vtc[j] - mu1) * rs1 * gamma[5 * HH + c] + beta[5 * HH + c];
        const float cg = tanhf(lnc);
        const float u = Ug[base + c];
        const float hv = h[base + c];
        out[base + c] = (1.0f - u) * hv + u * cg;
    }
}

// ---------------- launch ----------------
extern "C" void kernel_launch(void* const* d_in, const int* in_sizes, int n_in,
                              void* d_out, int out_size) {
    const float* x     = (const float*)d_in[0];
    const float* h     = (const float*)d_in[1];
    const float* W[6]  = {(const float*)d_in[2], (const float*)d_in[3],
                          (const float*)d_in[4], (const float*)d_in[5],
                          (const float*)d_in[6], (const float*)d_in[7]};
    const float* gamma = (const float*)d_in[8];
    const float* beta  = (const float*)d_in[9];
    float* out = (float*)d_out;

    float *Sr, *Tr, *Su, *Tu, *Tc, *Sc, *Ug;
    cudaGetSymbolAddress((void**)&Sr, g_Sr);
    cudaGetSymbolAddress((void**)&Tr, g_Tr);
    cudaGetSymbolAddress((void**)&Su, g_Su);
    cudaGetSymbolAddress((void**)&Tu, g_Tu);
    cudaGetSymbolAddress((void**)&Tc, g_Tc);
    cudaGetSymbolAddress((void**)&Sc, g_Sc);
    cudaGetSymbolAddress((void**)&Ug, g_Ug);

    __half *xh, *hh, *hrh, *Wh;
    cudaGetSymbolAddress((void**)&xh, g_xh);
    cudaGetSymbolAddress((void**)&hh, g_hh);
    cudaGetSymbolAddress((void**)&hrh, g_hrh);
    cudaGetSymbolAddress((void**)&Wh, g_Wh);

    cudaFuncSetAttribute(gemm_h, cudaFuncAttributeMaxDynamicSharedMemorySize, GEMM_SMEM);

    // fp32 -> fp16 conversions
    {
        int n4 = BB * KK / 4;
        tohalf_kernel<<<(n4 + 255) / 256, 256>>>((const float4*)x, (uint2*)xh, n4);
        tohalf_kernel<<<(n4 + 255) / 256, 256>>>((const float4*)h, (uint2*)hh, n4);
        int w4 = HH * KK / 4;
        for (int i = 0; i < 6; i++)
            tohalf_kernel<<<(w4 + 255) / 256, 256>>>((const float4*)W[i],
                                                     (uint2*)(Wh + (long)i * HH * KK), w4);
    }

    dim3 gg(HH / BN, BB / BM);  // (8, 64)

    // W order: W_r, U_r, W_u, U_u, W_c, U_c -> indices 0..5
    gemm_h<<<gg, 256, GEMM_SMEM>>>(hh, Wh + 0L * HH * KK, Sr);
    gemm_h<<<gg, 256, GEMM_SMEM>>>(xh, Wh + 1L * HH * KK, Tr);
    gemm_h<<<gg, 256, GEMM_SMEM>>>(hh, Wh + 2L * HH * KK, Su);
    gemm_h<<<gg, 256, GEMM_SMEM>>>(xh, Wh + 3L * HH * KK, Tu);
    gemm_h<<<gg, 256, GEMM_SMEM>>>(xh, Wh + 5L * HH * KK, Tc);

    gates_kernel<<<BB, 256>>>(Sr, Tr, Su, Tu, h, gamma, beta, hrh, Ug);

    gemm_h<<<gg, 256, GEMM_SMEM>>>(hrh, Wh + 4L * HH * KK, Sc);

    final_kernel<<<BB, 256>>>(Sc, Tc, h, Ug, gamma, beta, out);
}

// round 5
// speedup vs baseline: 5.0689x; 1.0742x over previous
#include <cuda_runtime.h>
#include <cuda_fp16.h>
#include <cstdint>

#define BB 8192
#define HH 1024
#define KK 1024

// ---------------- scratch (__device__ globals; allocation-free) ----------------
static __device__ float g_Sr[BB * HH];
static __device__ float g_Tr[BB * HH];
static __device__ float g_Su[BB * HH];
static __device__ float g_Tu[BB * HH];
static __device__ float g_Tc[BB * HH];
static __device__ float g_Sc[BB * HH];
static __device__ float g_Ug[BB * HH];

static __device__ __half g_xh[BB * KK];
static __device__ __half g_hh[BB * HH];
static __device__ __half g_hrh[BB * HH];
static __device__ __half g_Wh[6][HH * KK];

// ---------------- PTX helpers (base ISA only: compute_103-safe) ----------------
__device__ __forceinline__ uint32_t smem_u32(const void* p) {
    uint32_t a;
    asm("{ .reg .u64 t; cvta.to.shared.u64 t, %1; cvt.u32.u64 %0, t; }" : "=r"(a) : "l"(p));
    return a;
}

#define CP_ASYNC16(dst, src) \
    asm volatile("cp.async.cg.shared.global [%0], [%1], 16;" :: "r"(dst), "l"(src))
#define CP_COMMIT() asm volatile("cp.async.commit_group;" ::: "memory")
#define CP_WAIT(n) asm volatile("cp.async.wait_group %0;" :: "n"(n) : "memory")

__device__ __forceinline__ void ldsm_x4(uint32_t* r, uint32_t a) {
    asm volatile("ldmatrix.sync.aligned.m8n8.x4.shared.b16 {%0,%1,%2,%3}, [%4];"
                 : "=r"(r[0]), "=r"(r[1]), "=r"(r[2]), "=r"(r[3]) : "r"(a));
}
__device__ __forceinline__ void ldsm_x2(uint32_t* r, uint32_t a) {
    asm volatile("ldmatrix.sync.aligned.m8n8.x2.shared.b16 {%0,%1}, [%2];"
                 : "=r"(r[0]), "=r"(r[1]) : "r"(a));
}

__device__ __forceinline__ void mma16816(float* d, const uint32_t* a, const uint32_t* b) {
    asm volatile(
        "mma.sync.aligned.m16n8k16.row.col.f32.f16.f16.f32 "
        "{%0,%1,%2,%3}, {%4,%5,%6,%7}, {%8,%9}, {%0,%1,%2,%3};"
        : "+f"(d[0]), "+f"(d[1]), "+f"(d[2]), "+f"(d[3])
        : "r"(a[0]), "r"(a[1]), "r"(a[2]), "r"(a[3]), "r"(b[0]), "r"(b[1]));
}

// ---------------- single-pass fp16 mma.sync GEMM ----------------
// C[M,N] = A[M,K] * W[N,K]^T, fp16 inputs, fp32 accumulate.
// Tile 128x128x32, 256 threads (warps 2Mx4N, warp tile 64x32), 3-stage cp.async.
#define BM 128
#define BN 128
#define BK 32
#define NCHUNK (KK / BK)          // 32
#define NSTAGE 3
#define RSTRIDE 80                // 64B data + 16B pad -> conflict-free ldmatrix phases
#define T_BYTES (128 * RSTRIDE)   // 10240 per tensor tile
#define OFF_A 0
#define OFF_B T_BYTES
#define STAGE_BYTES (2 * T_BYTES) // 20480
#define GEMM_SMEM (NSTAGE * STAGE_BYTES)  // 61440

struct GemmBatch {
    const __half* A[5];
    const __half* B[5];
    float* C[5];
};

__device__ __forceinline__ void load_stage(
    uint32_t sb, int stage, int kc, int tid, int bm, int bn,
    const __half* __restrict__ A, const __half* __restrict__ B) {
    const uint32_t su = sb + stage * STAGE_BYTES;
    const int row = tid >> 1;
    const int ch = (tid & 1) * 2;                 // 16B chunk 0 or 2
    const long koff = (long)kc * BK + ch * 8;     // element offset in K
    const uint32_t doff = row * RSTRIDE + ch * 16;

    const char* ga = (const char*)(A + (long)(bm + row) * KK + koff);
    const char* gb = (const char*)(B + (long)(bn + row) * KK + koff);

    CP_ASYNC16(su + OFF_A + doff, ga);   CP_ASYNC16(su + OFF_A + doff + 16, ga + 16);
    CP_ASYNC16(su + OFF_B + doff, gb);   CP_ASYNC16(su + OFF_B + doff + 16, gb + 16);
}

__device__ __forceinline__ void gemm_body(
    const __half* __restrict__ A, const __half* __restrict__ B, float* __restrict__ C,
    char* smem) {
    const uint32_t sb = smem_u32(smem);
    const int tid = threadIdx.x;
    const int wid = tid >> 5, lane = tid & 31;
    const int warp_m = wid >> 2;   // 0..1
    const int warp_n = wid & 3;    // 0..3
    const int bm = blockIdx.y * BM;
    const int bn = blockIdx.x * BN;

    float acc[4][4][4];
#pragma unroll
    for (int i = 0; i < 4; i++)
#pragma unroll
        for (int j = 0; j < 4; j++)
#pragma unroll
            for (int q = 0; q < 4; q++) acc[i][j][q] = 0.f;

    const uint32_t a_row = (warp_m * 64 + (lane & 15)) * RSTRIDE;
    const uint32_t a_ch16 = (lane >> 4) * 16;
    const uint32_t b_row = (warp_n * 32 + (lane & 7)) * RSTRIDE;
    const uint32_t b_ch16 = ((lane >> 3) & 1) * 16;

#pragma unroll
    for (int s = 0; s < NSTAGE; s++) {
        load_stage(sb, s, s, tid, bm, bn, A, B);
        CP_COMMIT();
    }

    for (int c = 0; c < NCHUNK; c++) {
        CP_WAIT(NSTAGE - 1);
        __syncthreads();

        const uint32_t su = sb + (c % NSTAGE) * STAGE_BYTES;
#pragma unroll
        for (int ks = 0; ks < 2; ks++) {
            const uint32_t kbase = ks * 32;

            uint32_t ah[4][4];
#pragma unroll
            for (int mt = 0; mt < 4; mt++)
                ldsm_x4(ah[mt], su + OFF_A + a_row + mt * 16 * RSTRIDE + kbase + a_ch16);
            uint32_t bh[4][2];
#pragma unroll
            for (int nt = 0; nt < 4; nt++)
                ldsm_x2(bh[nt], su + OFF_B + b_row + nt * 8 * RSTRIDE + kbase + b_ch16);
#pragma unroll
            for (int mt = 0; mt < 4; mt++)
#pragma unroll
                for (int nt = 0; nt < 4; nt++) mma16816(acc[mt][nt], ah[mt], bh[nt]);
        }

        __syncthreads();
        if (c + NSTAGE < NCHUNK)
            load_stage(sb, (c + NSTAGE) % NSTAGE, c + NSTAGE, tid, bm, bn, A, B);
        CP_COMMIT();  // keep group counting exact
    }

    const int gid = lane >> 2, tig = lane & 3;
#pragma unroll
    for (int mt = 0; mt < 4; mt++) {
        const int row0 = bm + warp_m * 64 + mt * 16 + gid;
#pragma unroll
        for (int nt = 0; nt < 4; nt++) {
            const int col = bn + warp_n * 32 + nt * 8 + tig * 2;
            *(float2*)(C + (long)row0 * HH + col) = make_float2(acc[mt][nt][0], acc[mt][nt][1]);
            *(float2*)(C + (long)(row0 + 8) * HH + col) = make_float2(acc[mt][nt][2], acc[mt][nt][3]);
        }
    }
}

// Batched over z: the 5 independent GEMMs in one launch (one 9-wave grid
// instead of five 2-wave grids -> less tail waste).
__global__ __launch_bounds__(256, 2) void gemm_batched(GemmBatch gb) {
    extern __shared__ char smem[];
    const int z = blockIdx.z;
    gemm_body(gb.A[z], gb.B[z], gb.C[z], smem);
}

__global__ __launch_bounds__(256, 2) void gemm_h(
    const __half* __restrict__ A, const __half* __restrict__ B, float* __restrict__ C) {
    extern __shared__ char smem[];
    gemm_body(A, B, C, smem);
}

// ---------------- fused fp32 -> fp16 convert (all 8 tensors, one launch) ----------------
#define NX4 (BB * KK / 4)     // float4 count for x (and h)
#define NW4 (HH * KK / 4)     // float4 count per weight
#define NTOT4 (2 * NX4 + 6 * NW4)

struct ConvBatch {
    const float4* x;
    const float4* h;
    const float4* W[6];
    uint2* xh;
    uint2* hh;
    uint2* Wh;  // 6 contiguous planes
};

__global__ __launch_bounds__(256) void tohalf_all(ConvBatch cb) {
    int i = blockIdx.x * blockDim.x + threadIdx.x;
    if (i >= NTOT4) return;
    const float4* src;
    uint2* dst;
    if (i < NX4) {
        src = cb.x + i; dst = cb.xh + i;
    } else if (i < 2 * NX4) {
        int j = i - NX4;
        src = cb.h + j; dst = cb.hh + j;
    } else {
        int j = i - 2 * NX4;
        int w = j / NW4, k = j % NW4;
        src = cb.W[w] + k;
        dst = cb.Wh + (long)w * NW4 + k;
    }
    float4 v = *src;
    __half2 a = __floats2half2_rn(v.x, v.y);
    __half2 b = __floats2half2_rn(v.z, v.w);
    uint2 o;
    o.x = *(uint32_t*)&a;
    o.y = *(uint32_t*)&b;
    *dst = o;
}

// ---------------- reductions ----------------
__device__ __forceinline__ float warp_sum(float v) {
#pragma unroll
    for (int o = 16; o > 0; o >>= 1) v += __shfl_xor_sync(0xffffffffu, v, o);
    return v;
}

__device__ __forceinline__ void block_reduce8(float* p, float* s, int tid) {
    __shared__ float red[8][8];
    const int lane = tid & 31, w = tid >> 5;
#pragma unroll
    for (int q = 0; q < 8; q++) p[q] = warp_sum(p[q]);
    if (lane == 0) {
#pragma unroll
        for (int q = 0; q < 8; q++) red[q][w] = p[q];
    }
    __syncthreads();
    if (tid < 8) {
        float acc = 0.f;
#pragma unroll
        for (int w2 = 0; w2 < 8; w2++) acc += red[tid][w2];
        red[tid][0] = acc;
    }
    __syncthreads();
#pragma unroll
    for (int q = 0; q < 8; q++) s[q] = red[q][0];
}

__device__ __forceinline__ float sigmoidf_(float z) { return 1.0f / (1.0f + expf(-z)); }

// ---------------- gates: r,u; HR = h*r emitted as fp16 ----------------
__global__ __launch_bounds__(256) void gates_kernel(
    const float* __restrict__ Sr, const float* __restrict__ Tr,
    const float* __restrict__ Su, const float* __restrict__ Tu,
    const float* __restrict__ h,
    const float* __restrict__ gamma, const float* __restrict__ beta,
    __half* __restrict__ HRh, float* __restrict__ Ug) {
    const int row = blockIdx.x;
    const int tid = threadIdx.x;
    const long base = (long)row * HH;

    float vsr[4], vtr[4], vsu[4], vtu[4];
    float p[8];
#pragma unroll
    for (int q = 0; q < 8; q++) p[q] = 0.f;

#pragma unroll
    for (int j = 0; j < 4; j++) {
        const int c = tid + j * 256;
        float a = Sr[base + c]; vsr[j] = a; p[0] += a; p[1] += a * a;
        float b = Tr[base + c]; vtr[j] = b; p[2] += b; p[3] += b * b;
        float d = Su[base + c]; vsu[j] = d; p[4] += d; p[5] += d * d;
        float e = Tu[base + c]; vtu[j] = e; p[6] += e; p[7] += e * e;
    }

    float s[8];
    block_reduce8(p, s, tid);

    const float inv = 1.0f / (float)HH;
    const float mu0 = s[0] * inv, rs0 = rsqrtf(fmaxf(s[1] * inv - mu0 * mu0, 0.f) + 1e-5f);
    const float mu1 = s[2] * inv, rs1 = rsqrtf(fmaxf(s[3] * inv - mu1 * mu1, 0.f) + 1e-5f);
    const float mu2 = s[4] * inv, rs2 = rsqrtf(fmaxf(s[5] * inv - mu2 * mu2, 0.f) + 1e-5f);
    const float mu3 = s[6] * inv, rs3 = rsqrtf(fmaxf(s[7] * inv - mu3 * mu3, 0.f) + 1e-5f);

#pragma unroll
    for (int j = 0; j < 4; j++) {
        const int c = tid + j * 256;
        const float lnr = (vsr[j] - mu0) * rs0 * gamma[0 * HH + c] + beta[0 * HH + c]
                        + (vtr[j] - mu1) * rs1 * gamma[1 * HH + c] + beta[1 * HH + c];
        const float r = sigmoidf_(lnr);
        const float lnu = (vsu[j] - mu2) * rs2 * gamma[2 * HH + c] + beta[2 * HH + c]
                        + (vtu[j] - mu3) * rs3 * gamma[3 * HH + c] + beta[3 * HH + c];
        const float u = sigmoidf_(lnu);
        const float hr = h[base + c] * r;
        HRh[base + c] = __float2half_rn(hr);
        Ug[base + c] = u;
    }
}

// ---------------- final: c = tanh(ln+ln); out = (1-u)h + u*c ----------------
__global__ __launch_bounds__(256) void final_kernel(
    const float* __restrict__ Sc, const float* __restrict__ Tc,
    const float* __restrict__ h, const float* __restrict__ Ug,
    const float* __restrict__ gamma, const float* __restrict__ beta,
    float* __restrict__ out) {
    const int row = blockIdx.x;
    const int tid = threadIdx.x;
    const long base = (long)row * HH;

    float vsc[4], vtc[4];
    float p[8];
#pragma unroll
    for (int q = 0; q < 8; q++) p[q] = 0.f;

#pragma unroll
    for (int j = 0; j < 4; j++) {
        const int c = tid + j * 256;
        float a = Sc[base + c]; vsc[j] = a; p[0] += a; p[1] += a * a;
        float b = Tc[base + c]; vtc[j] = b; p[2] += b; p[3] += b * b;
    }

    float s[8];
    block_reduce8(p, s, tid);

    const float inv = 1.0f / (float)HH;
    const float mu0 = s[0] * inv, rs0 = rsqrtf(fmaxf(s[1] * inv - mu0 * mu0, 0.f) + 1e-5f);
    const float mu1 = s[2] * inv, rs1 = rsqrtf(fmaxf(s[3] * inv - mu1 * mu1, 0.f) + 1e-5f);

#pragma unroll
    for (int j = 0; j < 4; j++) {
        const int c = tid + j * 256;
        const float lnc = (vsc[j] - mu0) * rs0 * gamma[4 * HH + c] + beta[4 * HH + c]
                        + (vtc[j] - mu1) * rs1 * gamma[5 * HH + c] + beta[5 * HH + c];
        const float cg = tanhf(lnc);
        const float u = Ug[base + c];
        const float hv = h[base + c];
        out[base + c] = (1.0f - u) * hv + u * cg;
    }
}

// ---------------- launch ----------------
extern "C" void kernel_launch(void* const* d_in, const int* in_sizes, int n_in,
                              void* d_out, int out_size) {
    const float* x     = (const float*)d_in[0];
    const float* h     = (const float*)d_in[1];
    const float* W[6]  = {(const float*)d_in[2], (const float*)d_in[3],
                          (const float*)d_in[4], (const float*)d_in[5],
                          (const float*)d_in[6], (const float*)d_in[7]};
    const float* gamma = (const float*)d_in[8];
    const float* beta  = (const float*)d_in[9];
    float* out = (float*)d_out;

    float *Sr, *Tr, *Su, *Tu, *Tc, *Sc, *Ug;
    cudaGetSymbolAddress((void**)&Sr, g_Sr);
    cudaGetSymbolAddress((void**)&Tr, g_Tr);
    cudaGetSymbolAddress((void**)&Su, g_Su);
    cudaGetSymbolAddress((void**)&Tu, g_Tu);
    cudaGetSymbolAddress((void**)&Tc, g_Tc);
    cudaGetSymbolAddress((void**)&Sc, g_Sc);
    cudaGetSymbolAddress((void**)&Ug, g_Ug);

    __half *xh, *hh, *hrh, *Wh;
    cudaGetSymbolAddress((void**)&xh, g_xh);
    cudaGetSymbolAddress((void**)&hh, g_hh);
    cudaGetSymbolAddress((void**)&hrh, g_hrh);
    cudaGetSymbolAddress((void**)&Wh, g_Wh);

    cudaFuncSetAttribute(gemm_batched, cudaFuncAttributeMaxDynamicSharedMemorySize, GEMM_SMEM);
    cudaFuncSetAttribute(gemm_h, cudaFuncAttributeMaxDynamicSharedMemorySize, GEMM_SMEM);

    // one fused conversion launch for x, h, and all 6 weights
    {
        ConvBatch cb;
        cb.x = (const float4*)x;
        cb.h = (const float4*)h;
        for (int i = 0; i < 6; i++) cb.W[i] = (const float4*)W[i];
        cb.xh = (uint2*)xh;
        cb.hh = (uint2*)hh;
        cb.Wh = (uint2*)Wh;
        tohalf_all<<<(NTOT4 + 255) / 256, 256>>>(cb);
    }

    // 5 independent GEMMs in one batched launch
    {
        GemmBatch gb;
        // W order: W_r, U_r, W_u, U_u, W_c, U_c -> indices 0..5
        gb.A[0] = hh; gb.B[0] = Wh + 0L * HH * KK; gb.C[0] = Sr;
        gb.A[1] = xh; gb.B[1] = Wh + 1L * HH * KK; gb.C[1] = Tr;
        gb.A[2] = hh; gb.B[2] = Wh + 2L * HH * KK; gb.C[2] = Su;
        gb.A[3] = xh; gb.B[3] = Wh + 3L * HH * KK; gb.C[3] = Tu;
        gb.A[4] = xh; gb.B[4] = Wh + 5L * HH * KK; gb.C[4] = Tc;
        dim3 gg(HH / BN, BB / BM, 5);  // (8, 64, 5)
        gemm_batched<<<gg, 256, GEMM_SMEM>>>(gb);
    }

    gates_kernel<<<BB, 256>>>(Sr, Tr, Su, Tu, h, gamma, beta, hrh, Ug);

    {
        dim3 gg(HH / BN, BB / BM);
        gemm_h<<<gg, 256, GEMM_SMEM>>>(hrh, Wh + 4L * HH * KK, Sc);
    }

    final_kernel<<<BB, 256>>>(Sc, Tc, h, Ug, gamma, beta, out);
}

// round 6
// speedup vs baseline: 5.3149x; 1.0485x over previous
#include <cuda_runtime.h>
#include <cuda_fp16.h>
#include <cstdint>

#define BB 8192
#define HH 1024
#define KK 1024

// ---------------- scratch (__device__ globals; allocation-free) ----------------
static __device__ __half g_Sr[BB * HH];
static __device__ __half g_Tr[BB * HH];
static __device__ __half g_Su[BB * HH];
static __device__ __half g_Tu[BB * HH];
static __device__ __half g_Tc[BB * HH];
static __device__ __half g_Sc[BB * HH];
static __device__ __half g_Ug[BB * HH];

static __device__ __half g_xh[BB * KK];
static __device__ __half g_hh[BB * HH];
static __device__ __half g_hrh[BB * HH];
static __device__ __half g_Wh[6][HH * KK];

// ---------------- PTX helpers (base ISA only: compute_103-safe) ----------------
__device__ __forceinline__ uint32_t smem_u32(const void* p) {
    uint32_t a;
    asm("{ .reg .u64 t; cvta.to.shared.u64 t, %1; cvt.u32.u64 %0, t; }" : "=r"(a) : "l"(p));
    return a;
}

#define CP_ASYNC16(dst, src) \
    asm volatile("cp.async.cg.shared.global [%0], [%1], 16;" :: "r"(dst), "l"(src))
#define CP_COMMIT() asm volatile("cp.async.commit_group;" ::: "memory")
#define CP_WAIT(n) asm volatile("cp.async.wait_group %0;" :: "n"(n) : "memory")

__device__ __forceinline__ void ldsm_x4(uint32_t* r, uint32_t a) {
    asm volatile("ldmatrix.sync.aligned.m8n8.x4.shared.b16 {%0,%1,%2,%3}, [%4];"
                 : "=r"(r[0]), "=r"(r[1]), "=r"(r[2]), "=r"(r[3]) : "r"(a));
}

__device__ __forceinline__ void mma16816(float* d, const uint32_t* a, const uint32_t* b) {
    asm volatile(
        "mma.sync.aligned.m16n8k16.row.col.f32.f16.f16.f32 "
        "{%0,%1,%2,%3}, {%4,%5,%6,%7}, {%8,%9}, {%0,%1,%2,%3};"
        : "+f"(d[0]), "+f"(d[1]), "+f"(d[2]), "+f"(d[3])
        : "r"(a[0]), "r"(a[1]), "r"(a[2]), "r"(a[3]), "r"(b[0]), "r"(b[1]));
}

// ---------------- single-pass fp16 mma.sync GEMM ----------------
// C[M,N] = A[M,K] * W[N,K]^T, fp16 in, fp32 acc, fp16 out.
// Tile 128x128x32, 256 threads (warps 2Mx4N, warp tile 64x32), 4-stage cp.async,
// ONE barrier per chunk, all fragments loaded up-front per chunk.
#define BM 128
#define BN 128
#define BK 32
#define NCHUNK (KK / BK)          // 32
#define NSTAGE 4
#define RSTRIDE 80                // 64B data + 16B pad -> conflict-free ldmatrix phases
#define T_BYTES (128 * RSTRIDE)   // 10240 per tensor tile
#define OFF_A 0
#define OFF_B T_BYTES
#define STAGE_BYTES (2 * T_BYTES) // 20480
#define GEMM_SMEM (NSTAGE * STAGE_BYTES)  // 81920

struct GemmBatch {
    const __half* A[5];
    const __half* B[5];
    __half* C[5];
};

__device__ __forceinline__ void load_stage(
    uint32_t sb, int stage, int kc, int tid, int bm, int bn,
    const __half* __restrict__ A, const __half* __restrict__ B) {
    const uint32_t su = sb + stage * STAGE_BYTES;
    const int row = tid >> 1;
    const int ch = (tid & 1) * 2;                 // 16B chunk 0 or 2
    const long koff = (long)kc * BK + ch * 8;     // element offset in K
    const uint32_t doff = row * RSTRIDE + ch * 16;

    const char* ga = (const char*)(A + (long)(bm + row) * KK + koff);
    const char* gb = (const char*)(B + (long)(bn + row) * KK + koff);

    CP_ASYNC16(su + OFF_A + doff, ga);   CP_ASYNC16(su + OFF_A + doff + 16, ga + 16);
    CP_ASYNC16(su + OFF_B + doff, gb);   CP_ASYNC16(su + OFF_B + doff + 16, gb + 16);
}

__device__ __forceinline__ void gemm_body(
    const __half* __restrict__ A, const __half* __restrict__ B, __half* __restrict__ C,
    char* smem) {
    const uint32_t sb = smem_u32(smem);
    const int tid = threadIdx.x;
    const int wid = tid >> 5, lane = tid & 31;
    const int warp_m = wid >> 2;   // 0..1
    const int warp_n = wid & 3;    // 0..3
    const int bm = blockIdx.y * BM;
    const int bn = blockIdx.x * BN;

    float acc[4][4][4];
#pragma unroll
    for (int i = 0; i < 4; i++)
#pragma unroll
        for (int j = 0; j < 4; j++)
#pragma unroll
            for (int q = 0; q < 4; q++) acc[i][j][q] = 0.f;

    // A: per-kstep x4 (16 rows x 16 halves); lanes 16-31 take second 16B column
    const uint32_t a_off = (warp_m * 64 + (lane & 15)) * RSTRIDE + (lane >> 4) * 16;
    // B: one x4 spans BOTH ksteps (4 16B columns = k0..31); lane>>3 selects column
    const uint32_t b_off = (warp_n * 32 + (lane & 7)) * RSTRIDE + (lane >> 3) * 16;

#pragma unroll
    for (int s = 0; s < NSTAGE - 1; s++) {
        load_stage(sb, s, s, tid, bm, bn, A, B);
        CP_COMMIT();
    }

    for (int c = 0; c < NCHUNK; c++) {
        CP_WAIT(NSTAGE - 2);
        __syncthreads();

        // refill the stage consumed at c-1 (safe: all warps passed the barrier)
        if (c + NSTAGE - 1 < NCHUNK)
            load_stage(sb, (c + NSTAGE - 1) % NSTAGE, c + NSTAGE - 1, tid, bm, bn, A, B);
        CP_COMMIT();

        const uint32_t su = sb + (c % NSTAGE) * STAGE_BYTES;

        // load all fragments for the whole chunk up-front (max ILP)
        uint32_t bb[4][4];
#pragma unroll
        for (int nt = 0; nt < 4; nt++)
            ldsm_x4(bb[nt], su + OFF_B + b_off + nt * 8 * RSTRIDE);
        uint32_t a0[4][4], a1[4][4];
#pragma unroll
        for (int mt = 0; mt < 4; mt++)
            ldsm_x4(a0[mt], su + OFF_A + a_off + mt * 16 * RSTRIDE);
#pragma unroll
        for (int mt = 0; mt < 4; mt++)
            ldsm_x4(a1[mt], su + OFF_A + a_off + mt * 16 * RSTRIDE + 32);

#pragma unroll
        for (int mt = 0; mt < 4; mt++)
#pragma unroll
            for (int nt = 0; nt < 4; nt++) mma16816(acc[mt][nt], a0[mt], &bb[nt][0]);
#pragma unroll
        for (int mt = 0; mt < 4; mt++)
#pragma unroll
            for (int nt = 0; nt < 4; nt++) mma16816(acc[mt][nt], a1[mt], &bb[nt][2]);
    }

    // epilogue: fp32 acc -> fp16 stores
    const int gid = lane >> 2, tig = lane & 3;
#pragma unroll
    for (int mt = 0; mt < 4; mt++) {
        const int row0 = bm + warp_m * 64 + mt * 16 + gid;
#pragma unroll
        for (int nt = 0; nt < 4; nt++) {
            const int col = bn + warp_n * 32 + nt * 8 + tig * 2;
            __half2 v0 = __floats2half2_rn(acc[mt][nt][0], acc[mt][nt][1]);
            __half2 v1 = __floats2half2_rn(acc[mt][nt][2], acc[mt][nt][3]);
            *(__half2*)(C + (long)row0 * HH + col) = v0;
            *(__half2*)(C + (long)(row0 + 8) * HH + col) = v1;
        }
    }
}

__global__ __launch_bounds__(256, 2) void gemm_batched(GemmBatch gb) {
    extern __shared__ char smem[];
    const int z = blockIdx.z;
    gemm_body(gb.A[z], gb.B[z], gb.C[z], smem);
}

__global__ __launch_bounds__(256, 2) void gemm_h(
    const __half* __restrict__ A, const __half* __restrict__ B, __half* __restrict__ C) {
    extern __shared__ char smem[];
    gemm_body(A, B, C, smem);
}

// ---------------- fused fp32 -> fp16 convert (all 8 tensors, one launch) ----------------
#define NX4 (BB * KK / 4)
#define NW4 (HH * KK / 4)
#define NTOT4 (2 * NX4 + 6 * NW4)

struct ConvBatch {
    const float4* x;
    const float4* h;
    const float4* W[6];
    uint2* xh;
    uint2* hh;
    uint2* Wh;  // 6 contiguous planes
};

__global__ __launch_bounds__(256) void tohalf_all(ConvBatch cb) {
    int i = blockIdx.x * blockDim.x + threadIdx.x;
    if (i >= NTOT4) return;
    const float4* src;
    uint2* dst;
    if (i < NX4) {
        src = cb.x + i; dst = cb.xh + i;
    } else if (i < 2 * NX4) {
        int j = i - NX4;
        src = cb.h + j; dst = cb.hh + j;
    } else {
        int j = i - 2 * NX4;
        int w = j / NW4, k = j % NW4;
        src = cb.W[w] + k;
        dst = cb.Wh + (long)w * NW4 + k;
    }
    float4 v = *src;
    __half2 a = __floats2half2_rn(v.x, v.y);
    __half2 b = __floats2half2_rn(v.z, v.w);
    uint2 o;
    o.x = *(uint32_t*)&a;
    o.y = *(uint32_t*)&b;
    *dst = o;
}

// ---------------- reductions ----------------
__device__ __forceinline__ float warp_sum(float v) {
#pragma unroll
    for (int o = 16; o > 0; o >>= 1) v += __shfl_xor_sync(0xffffffffu, v, o);
    return v;
}

__device__ __forceinline__ void block_reduce8(float* p, float* s, int tid) {
    __shared__ float red[8][8];
    const int lane = tid & 31, w = tid >> 5;
#pragma unroll
    for (int q = 0; q < 8; q++) p[q] = warp_sum(p[q]);
    if (lane == 0) {
#pragma unroll
        for (int q = 0; q < 8; q++) red[q][w] = p[q];
    }
    __syncthreads();
    if (tid < 8) {
        float acc = 0.f;
#pragma unroll
        for (int w2 = 0; w2 < 8; w2++) acc += red[tid][w2];
        red[tid][0] = acc;
    }
    __syncthreads();
#pragma unroll
    for (int q = 0; q < 8; q++) s[q] = red[q][0];
}

__device__ __forceinline__ float sigmoidf_(float z) { return 1.0f / (1.0f + expf(-z)); }

// ---------------- gates: r,u; HR = h*r emitted as fp16 ----------------
__global__ __launch_bounds__(256) void gates_kernel(
    const __half* __restrict__ Sr, const __half* __restrict__ Tr,
    const __half* __restrict__ Su, const __half* __restrict__ Tu,
    const float* __restrict__ h,
    const float* __restrict__ gamma, const float* __restrict__ beta,
    __half* __restrict__ HRh, __half* __restrict__ Ug) {
    const int row = blockIdx.x;
    const int tid = threadIdx.x;
    const long base = (long)row * HH;

    float vsr[4], vtr[4], vsu[4], vtu[4];
    float p[8];
#pragma unroll
    for (int q = 0; q < 8; q++) p[q] = 0.f;

#pragma unroll
    for (int j = 0; j < 4; j++) {
        const int c = tid + j * 256;
        float a = __half2float(Sr[base + c]); vsr[j] = a; p[0] += a; p[1] += a * a;
        float b = __half2float(Tr[base + c]); vtr[j] = b; p[2] += b; p[3] += b * b;
        float d = __half2float(Su[base + c]); vsu[j] = d; p[4] += d; p[5] += d * d;
        float e = __half2float(Tu[base + c]); vtu[j] = e; p[6] += e; p[7] += e * e;
    }

    float s[8];
    block_reduce8(p, s, tid);

    const float inv = 1.0f / (float)HH;
    const float mu0 = s[0] * inv, rs0 = rsqrtf(fmaxf(s[1] * inv - mu0 * mu0, 0.f) + 1e-5f);
    const float mu1 = s[2] * inv, rs1 = rsqrtf(fmaxf(s[3] * inv - mu1 * mu1, 0.f) + 1e-5f);
    const float mu2 = s[4] * inv, rs2 = rsqrtf(fmaxf(s[5] * inv - mu2 * mu2, 0.f) + 1e-5f);
    const float mu3 = s[6] * inv, rs3 = rsqrtf(fmaxf(s[7] * inv - mu3 * mu3, 0.f) + 1e-5f);

#pragma unroll
    for (int j = 0; j < 4; j++) {
        const int c = tid + j * 256;
        const float lnr = (vsr[j] - mu0) * rs0 * gamma[0 * HH + c] + beta[0 * HH + c]
                        + (vtr[j] - mu1) * rs1 * gamma[1 * HH + c] + beta[1 * HH + c];
        const float r = sigmoidf_(lnr);
        const float lnu = (vsu[j] - mu2) * rs2 * gamma[2 * HH + c] + beta[2 * HH + c]
                        + (vtu[j] - mu3) * rs3 * gamma[3 * HH + c] + beta[3 * HH + c];
        const float u = sigmoidf_(lnu);
        const float hr = h[base + c] * r;
        HRh[base + c] = __float2half_rn(hr);
        Ug[base + c] = __float2half_rn(u);
    }
}

// ---------------- final: c = tanh(ln+ln); out = (1-u)h + u*c ----------------
__global__ __launch_bounds__(256) void final_kernel(
    const __half* __restrict__ Sc, const __half* __restrict__ Tc,
    const float* __restrict__ h, const __half* __restrict__ Ug,
    const float* __restrict__ gamma, const float* __restrict__ beta,
    float* __restrict__ out) {
    const int row = blockIdx.x;
    const int tid = threadIdx.x;
    const long base = (long)row * HH;

    float vsc[4], vtc[4];
    float p[8];
#pragma unroll
    for (int q = 0; q < 8; q++) p[q] = 0.f;

#pragma unroll
    for (int j = 0; j < 4; j++) {
        const int c = tid + j * 256;
        float a = __half2float(Sc[base + c]); vsc[j] = a; p[0] += a; p[1] += a * a;
        float b = __half2float(Tc[base + c]); vtc[j] = b; p[2] += b; p[3] += b * b;
    }

    float s[8];
    block_reduce8(p, s, tid);

    const float inv = 1.0f / (float)HH;
    const float mu0 = s[0] * inv, rs0 = rsqrtf(fmaxf(s[1] * inv - mu0 * mu0, 0.f) + 1e-5f);
    const float mu1 = s[2] * inv, rs1 = rsqrtf(fmaxf(s[3] * inv - mu1 * mu1, 0.f) + 1e-5f);

#pragma unroll
    for (int j = 0; j < 4; j++) {
        const int c = tid + j * 256;
        const float lnc = (vsc[j] - mu0) * rs0 * gamma[4 * HH + c] + beta[4 * HH + c]
                        + (vtc[j] - mu1) * rs1 * gamma[5 * HH + c] + beta[5 * HH + c];
        const float cg = tanhf(lnc);
        const float u = __half2float(Ug[base + c]);
        const float hv = h[base + c];
        out[base + c] = (1.0f - u) * hv + u * cg;
    }
}

// ---------------- launch ----------------
extern "C" void kernel_launch(void* const* d_in, const int* in_sizes, int n_in,
                              void* d_out, int out_size) {
    const float* x     = (const float*)d_in[0];
    const float* h     = (const float*)d_in[1];
    const float* W[6]  = {(const float*)d_in[2], (const float*)d_in[3],
                          (const float*)d_in[4], (const float*)d_in[5],
                          (const float*)d_in[6], (const float*)d_in[7]};
    const float* gamma = (const float*)d_in[8];
    const float* beta  = (const float*)d_in[9];
    float* out = (float*)d_out;

    __half *Sr, *Tr, *Su, *Tu, *Tc, *Sc, *Ug;
    cudaGetSymbolAddress((void**)&Sr, g_Sr);
    cudaGetSymbolAddress((void**)&Tr, g_Tr);
    cudaGetSymbolAddress((void**)&Su, g_Su);
    cudaGetSymbolAddress((void**)&Tu, g_Tu);
    cudaGetSymbolAddress((void**)&Tc, g_Tc);
    cudaGetSymbolAddress((void**)&Sc, g_Sc);
    cudaGetSymbolAddress((void**)&Ug, g_Ug);

    __half *xh, *hh, *hrh, *Wh;
    cudaGetSymbolAddress((void**)&xh, g_xh);
    cudaGetSymbolAddress((void**)&hh, g_hh);
    cudaGetSymbolAddress((void**)&hrh, g_hrh);
    cudaGetSymbolAddress((void**)&Wh, g_Wh);

    cudaFuncSetAttribute(gemm_batched, cudaFuncAttributeMaxDynamicSharedMemorySize, GEMM_SMEM);
    cudaFuncSetAttribute(gemm_h, cudaFuncAttributeMaxDynamicSharedMemorySize, GEMM_SMEM);

    // one fused conversion launch for x, h, and all 6 weights
    {
        ConvBatch cb;
        cb.x = (const float4*)x;
        cb.h = (const float4*)h;
        for (int i = 0; i < 6; i++) cb.W[i] = (const float4*)W[i];
        cb.xh = (uint2*)xh;
        cb.hh = (uint2*)hh;
        cb.Wh = (uint2*)Wh;
        tohalf_all<<<(NTOT4 + 255) / 256, 256>>>(cb);
    }

    // 5 independent GEMMs in one batched launch
    {
        GemmBatch gb;
        // W order: W_r, U_r, W_u, U_u, W_c, U_c -> indices 0..5
        gb.A[0] = hh; gb.B[0] = Wh + 0L * HH * KK; gb.C[0] = Sr;
        gb.A[1] = xh; gb.B[1] = Wh + 1L * HH * KK; gb.C[1] = Tr;
        gb.A[2] = hh; gb.B[2] = Wh + 2L * HH * KK; gb.C[2] = Su;
        gb.A[3] = xh; gb.B[3] = Wh + 3L * HH * KK; gb.C[3] = Tu;
        gb.A[4] = xh; gb.B[4] = Wh + 5L * HH * KK; gb.C[4] = Tc;
        dim3 gg(HH / BN, BB / BM, 5);  // (8, 64, 5)
        gemm_batched<<<gg, 256, GEMM_SMEM>>>(gb);
    }

    gates_kernel<<<BB, 256>>>(Sr, Tr, Su, Tu, h, gamma, beta, hrh, Ug);

    {
        dim3 gg(HH / BN, BB / BM);
        gemm_h<<<gg, 256, GEMM_SMEM>>>(hrh, Wh + 4L * HH * KK, Sc);
    }

    final_kernel<<<BB, 256>>>(Sc, Tc, h, Ug, gamma, beta, out);
}